// round 2
// baseline (speedup 1.0000x reference)
#include <cuda_runtime.h>
#include <cuda_bf16.h>
#include <cstdint>

// Problem constants
#define T_TOK 4096
#define D_MODEL 1024
#define NH 16
#define DK 64
#define QKV_N 3072
#define ATT_SCALE 0.125f   // 1/sqrt(64)

// Scratch (allocation-free rule: __device__ globals)
__device__ float g_qkv[T_TOK * QKV_N];    // [t, 3*1024] : q|k|v each [t, h*64+dk]
__device__ float g_attn[T_TOK * D_MODEL]; // attention output [t, h*64+dk]

// ---------------------------------------------------------------------------
// SGEMM (NT): C[m,n] = sum_k A[m,k] * B[n,k]
// 128x128 block tile, BK=8, 256 threads, 8x8 per thread.
// ---------------------------------------------------------------------------
#define BM 128
#define BN 128
#define BK 8

__global__ __launch_bounds__(256) void sgemm_nt(const float* __restrict__ A,
                                                const float* __restrict__ B,
                                                float* __restrict__ C,
                                                int M, int N, int K) {
    __shared__ float As[BK][BM];
    __shared__ float Bs[BK][BN];

    const int bx = blockIdx.x;  // N tile
    const int by = blockIdx.y;  // M tile
    const int tid = threadIdx.x;
    const int tx = tid & 15;    // 0..15 -> 8 cols each
    const int ty = tid >> 4;    // 0..15 -> 8 rows each

    // global load mapping: each thread loads one float4 of A and one of B
    const int lrow = tid >> 1;        // 0..127
    const int lcol = (tid & 1) * 4;   // 0 or 4

    const float* Ag = A + (size_t)(by * BM + lrow) * K + lcol;
    const float* Bg = B + (size_t)(bx * BN + lrow) * K + lcol;

    float acc[8][8];
#pragma unroll
    for (int i = 0; i < 8; i++)
#pragma unroll
        for (int j = 0; j < 8; j++) acc[i][j] = 0.f;

    for (int k0 = 0; k0 < K; k0 += BK) {
        float4 av = *reinterpret_cast<const float4*>(Ag + k0);
        float4 bv = *reinterpret_cast<const float4*>(Bg + k0);
        As[lcol + 0][lrow] = av.x;
        As[lcol + 1][lrow] = av.y;
        As[lcol + 2][lrow] = av.z;
        As[lcol + 3][lrow] = av.w;
        Bs[lcol + 0][lrow] = bv.x;
        Bs[lcol + 1][lrow] = bv.y;
        Bs[lcol + 2][lrow] = bv.z;
        Bs[lcol + 3][lrow] = bv.w;
        __syncthreads();

#pragma unroll
        for (int k = 0; k < BK; k++) {
            float4 a0 = *reinterpret_cast<const float4*>(&As[k][ty * 8]);
            float4 a1 = *reinterpret_cast<const float4*>(&As[k][ty * 8 + 4]);
            float4 b0 = *reinterpret_cast<const float4*>(&Bs[k][tx * 8]);
            float4 b1 = *reinterpret_cast<const float4*>(&Bs[k][tx * 8 + 4]);
            float a[8] = {a0.x, a0.y, a0.z, a0.w, a1.x, a1.y, a1.z, a1.w};
            float b[8] = {b0.x, b0.y, b0.z, b0.w, b1.x, b1.y, b1.z, b1.w};
#pragma unroll
            for (int i = 0; i < 8; i++)
#pragma unroll
                for (int j = 0; j < 8; j++) acc[i][j] += a[i] * b[j];
        }
        __syncthreads();
    }

    // write back (vectorized)
#pragma unroll
    for (int i = 0; i < 8; i++) {
        float* Cr = C + (size_t)(by * BM + ty * 8 + i) * N + bx * BN + tx * 8;
        float4 c0 = {acc[i][0], acc[i][1], acc[i][2], acc[i][3]};
        float4 c1 = {acc[i][4], acc[i][5], acc[i][6], acc[i][7]};
        *reinterpret_cast<float4*>(Cr) = c0;
        *reinterpret_cast<float4*>(Cr + 4) = c1;
    }
}

// ---------------------------------------------------------------------------
// Causal attention with clamp(+/-10), fixed-max softmax: p = exp(clamp(s)-10).
// One block per (query tile of 64, head). 256 threads, 4x4 per thread.
// ---------------------------------------------------------------------------
#define AP 65   // smem row pad (floats)
#define ATT_SMEM_BYTES ((4 * 64 * AP + 64 * 17) * 4)

__global__ __launch_bounds__(256) void attn_kernel(const float* __restrict__ qkv,
                                                   float* __restrict__ outp) {
    extern __shared__ float sm[];
    float* Qs = sm;                 // 64 x AP
    float* Ks = Qs + 64 * AP;
    float* Vs = Ks + 64 * AP;
    float* Ps = Vs + 64 * AP;
    float* Lred = Ps + 64 * AP;     // 64 x 17

    const int h = blockIdx.y;
    const int qb = blockIdx.x;
    const int tid = threadIdx.x;
    const int tx = tid & 15;   // key/col group
    const int ty = tid >> 4;   // query/row group
    const int q0 = qb * 64;

    // Load Q tile [64 x 64]
    for (int i = tid; i < 64 * 64; i += 256) {
        int r = i >> 6, d = i & 63;
        Qs[r * AP + d] = qkv[(size_t)(q0 + r) * QKV_N + h * DK + d];
    }

    float o[4][4];
#pragma unroll
    for (int i = 0; i < 4; i++)
#pragma unroll
        for (int j = 0; j < 4; j++) o[i][j] = 0.f;
    float lpart[4] = {0.f, 0.f, 0.f, 0.f};

    for (int kb = 0; kb <= qb; ++kb) {
        const int k0 = kb * 64;
        __syncthreads();  // protect Ks/Vs/Ps from previous iteration readers (and Q load, iter 0)
        for (int i = tid; i < 64 * 64; i += 256) {
            int r = i >> 6, d = i & 63;
            size_t base = (size_t)(k0 + r) * QKV_N + h * DK + d;
            Ks[r * AP + d] = qkv[base + 1024];
            Vs[r * AP + d] = qkv[base + 2048];
        }
        __syncthreads();

        // S = Q K^T (4x4 per thread)
        float acc[4][4];
#pragma unroll
        for (int i = 0; i < 4; i++)
#pragma unroll
            for (int j = 0; j < 4; j++) acc[i][j] = 0.f;

#pragma unroll 16
        for (int d = 0; d < 64; ++d) {
            float a[4], b[4];
#pragma unroll
            for (int i = 0; i < 4; i++) a[i] = Qs[(ty * 4 + i) * AP + d];
#pragma unroll
            for (int j = 0; j < 4; j++) b[j] = Ks[(tx * 4 + j) * AP + d];
#pragma unroll
            for (int i = 0; i < 4; i++)
#pragma unroll
                for (int j = 0; j < 4; j++) acc[i][j] += a[i] * b[j];
        }

        const bool diag = (kb == qb);
#pragma unroll
        for (int i = 0; i < 4; i++) {
#pragma unroll
            for (int j = 0; j < 4; j++) {
                float s = acc[i][j] * ATT_SCALE;
                s = fminf(fmaxf(s, -10.f), 10.f);
                float p = __expf(s - 10.f);
                if (diag && (tx * 4 + j) > (ty * 4 + i)) p = 0.f;
                lpart[i] += p;
                Ps[(ty * 4 + i) * AP + tx * 4 + j] = p;
            }
        }
        __syncthreads();

        // O += P V
#pragma unroll 16
        for (int k = 0; k < 64; ++k) {
            float a[4], b[4];
#pragma unroll
            for (int i = 0; i < 4; i++) a[i] = Ps[(ty * 4 + i) * AP + k];
#pragma unroll
            for (int j = 0; j < 4; j++) b[j] = Vs[k * AP + tx * 4 + j];
#pragma unroll
            for (int i = 0; i < 4; i++)
#pragma unroll
                for (int j = 0; j < 4; j++) o[i][j] += a[i] * b[j];
        }
    }

    // Deterministic row-sum reduction
    __syncthreads();
#pragma unroll
    for (int i = 0; i < 4; i++) Lred[(ty * 4 + i) * 17 + tx] = lpart[i];
    __syncthreads();

#pragma unroll
    for (int i = 0; i < 4; i++) {
        float s = 0.f;
#pragma unroll
        for (int t = 0; t < 16; t++) s += Lred[(ty * 4 + i) * 17 + t];
        float inv = 1.f / s;
        float4 v0 = {o[i][0] * inv, o[i][1] * inv, o[i][2] * inv, o[i][3] * inv};
        float* dst = outp + (size_t)(q0 + ty * 4 + i) * D_MODEL + h * DK + tx * 4;
        *reinterpret_cast<float4*>(dst) = v0;
    }
}

// ---------------------------------------------------------------------------
// Launch
// ---------------------------------------------------------------------------
extern "C" void kernel_launch(void* const* d_in, const int* in_sizes, int n_in,
                              void* d_out, int out_size) {
    const float* x    = (const float*)d_in[0];   // [4096,1024]
    const float* Wqkv = (const float*)d_in[1];   // [3072,1024]
    const float* Wout = (const float*)d_in[2];   // [1024,1024]
    float* out = (float*)d_out;                  // [4096,1024]

    float* qkv = nullptr;
    float* attn = nullptr;
    cudaGetSymbolAddress((void**)&qkv, g_qkv);
    cudaGetSymbolAddress((void**)&attn, g_attn);

    cudaFuncSetAttribute(attn_kernel, cudaFuncAttributeMaxDynamicSharedMemorySize,
                         ATT_SMEM_BYTES);

    // 1) QKV projection: [4096,3072] = x @ Wqkv^T
    sgemm_nt<<<dim3(QKV_N / BN, T_TOK / BM), 256>>>(x, Wqkv, qkv, T_TOK, QKV_N, D_MODEL);

    // 2) Causal clamped attention
    attn_kernel<<<dim3(T_TOK / 64, NH), 256, ATT_SMEM_BYTES>>>(qkv, attn);

    // 3) Output projection: [4096,1024] = attn @ Wout^T
    sgemm_nt<<<dim3(D_MODEL / BN, T_TOK / BM), 256>>>(attn, Wout, out, T_TOK, D_MODEL, D_MODEL);
}

// round 3
// speedup vs baseline: 3.0085x; 3.0085x over previous
#include <cuda_runtime.h>
#include <cstdint>

#define T_TOK 4096
#define D_MODEL 1024
#define NH 16
#define QKV_N 3072

// Scratch (__device__ globals per allocation rules)
__device__ float g_qkv[T_TOK * QKV_N];      // rounded-tf32 q|k|v
__device__ float g_attn[T_TOK * D_MODEL];   // rounded-tf32 attention out
__device__ float g_xr[T_TOK * D_MODEL];     // rounded inputs
__device__ float g_wqkvr[QKV_N * D_MODEL];
__device__ float g_woutr[D_MODEL * D_MODEL];

// ---------------------------------------------------------------------------
// helpers
// ---------------------------------------------------------------------------
__device__ __forceinline__ uint32_t f2tf(float f) {
    uint32_t u; asm("cvt.rna.tf32.f32 %0, %1;" : "=r"(u) : "f"(f)); return u;
}
__device__ __forceinline__ void cp16(void* smem, const void* gmem) {
    uint32_t s = (uint32_t)__cvta_generic_to_shared(smem);
    asm volatile("cp.async.cg.shared.global [%0], [%1], 16;" :: "r"(s), "l"(gmem));
}
__device__ __forceinline__ void cp_commit() { asm volatile("cp.async.commit_group;"); }
template <int N> __device__ __forceinline__ void cp_wait() {
    asm volatile("cp.async.wait_group %0;" :: "n"(N));
}
// D += A*B, m16n8k8 tf32 (A row-major, B col-major)
__device__ __forceinline__ void mma8(float* c, uint32_t a0, uint32_t a1, uint32_t a2,
                                     uint32_t a3, uint32_t b0, uint32_t b1) {
    asm("mma.sync.aligned.m16n8k8.row.col.f32.tf32.tf32.f32 "
        "{%0,%1,%2,%3}, {%4,%5,%6,%7}, {%8,%9}, {%0,%1,%2,%3};"
        : "+f"(c[0]), "+f"(c[1]), "+f"(c[2]), "+f"(c[3])
        : "r"(a0), "r"(a1), "r"(a2), "r"(a3), "r"(b0), "r"(b1));
}

// ---------------------------------------------------------------------------
// elementwise rna(tf32) rounding
// ---------------------------------------------------------------------------
__global__ void round_k(const float4* __restrict__ in, float4* __restrict__ out, int n4) {
    int i = blockIdx.x * blockDim.x + threadIdx.x;
    if (i >= n4) return;
    float4 v = in[i];
    uint4 o = {f2tf(v.x), f2tf(v.y), f2tf(v.z), f2tf(v.w)};
    out[i] = *reinterpret_cast<float4*>(&o);
}

// ---------------------------------------------------------------------------
// tf32 tensor-core GEMM (NT): C[m,n] = sum_k A[m,k]*B[n,k]
// 128x128x32 block tile, 256 threads (8 warps, 2x4), cp.async double buffer.
// Inputs must already be tf32-rounded.
// ---------------------------------------------------------------------------
#define SA 36   // smem row stride (floats), conflict-free: (4m+k) mod 32
#define GEMM_SMEM (2 * 2 * 128 * SA * 4)

template <bool ROUND_OUT>
__global__ __launch_bounds__(256, 2) void gemm_tf32(const float* __restrict__ A,
                                                    const float* __restrict__ B,
                                                    float* __restrict__ C,
                                                    int M, int N, int K) {
    extern __shared__ float sm[];
    float* Abuf[2] = {sm, sm + 2 * 128 * SA};
    float* Bbuf[2] = {sm + 128 * SA, sm + 3 * 128 * SA};

    const int tid = threadIdx.x;
    const int wid = tid >> 5, lane = tid & 31;
    const int g = lane >> 2, tig = lane & 3;
    const int mW = (wid >> 2) * 64, nW = (wid & 3) * 32;
    const int by = blockIdx.y * 128, bx = blockIdx.x * 128;

    float acc[4][4][4];
#pragma unroll
    for (int a = 0; a < 4; a++)
#pragma unroll
        for (int b = 0; b < 4; b++)
#pragma unroll
            for (int c = 0; c < 4; c++) acc[a][b][c] = 0.f;

    const int nkt = K / 32;

    // tile loader: 128 rows x 32 floats = 1024 16B chunks per operand
    auto load_tile = [&](int kt, int buf) {
        const float* Ag = A + (size_t)by * K + kt * 32;
        const float* Bg = B + (size_t)bx * K + kt * 32;
#pragma unroll
        for (int i = 0; i < 4; i++) {
            int e = tid + 256 * i;
            int row = e >> 3, c = (e & 7) * 4;
            cp16(&Abuf[buf][row * SA + c], Ag + (size_t)row * K + c);
            cp16(&Bbuf[buf][row * SA + c], Bg + (size_t)row * K + c);
        }
        cp_commit();
    };

    load_tile(0, 0);
    for (int kt = 0; kt < nkt; kt++) {
        if (kt + 1 < nkt) {
            load_tile(kt + 1, (kt + 1) & 1);
            cp_wait<1>();
        } else {
            cp_wait<0>();
        }
        __syncthreads();
        const uint32_t* As = (const uint32_t*)Abuf[kt & 1];
        const uint32_t* Bs = (const uint32_t*)Bbuf[kt & 1];
#pragma unroll
        for (int ks = 0; ks < 4; ks++) {
            uint32_t af[4][4], bf[4][2];
#pragma unroll
            for (int mt = 0; mt < 4; mt++) {
                int r = mW + mt * 16 + g;
                af[mt][0] = As[r * SA + ks * 8 + tig];
                af[mt][1] = As[(r + 8) * SA + ks * 8 + tig];
                af[mt][2] = As[r * SA + ks * 8 + tig + 4];
                af[mt][3] = As[(r + 8) * SA + ks * 8 + tig + 4];
            }
#pragma unroll
            for (int nt = 0; nt < 4; nt++) {
                int r = nW + nt * 8 + g;
                bf[nt][0] = Bs[r * SA + ks * 8 + tig];
                bf[nt][1] = Bs[r * SA + ks * 8 + tig + 4];
            }
#pragma unroll
            for (int mt = 0; mt < 4; mt++)
#pragma unroll
                for (int nt = 0; nt < 4; nt++)
                    mma8(acc[mt][nt], af[mt][0], af[mt][1], af[mt][2], af[mt][3],
                         bf[nt][0], bf[nt][1]);
        }
        __syncthreads();
    }

#pragma unroll
    for (int mt = 0; mt < 4; mt++) {
#pragma unroll
        for (int nt = 0; nt < 4; nt++) {
            int row = by + mW + mt * 16 + g;
            int col = bx + nW + nt * 8 + tig * 2;
            float v0 = acc[mt][nt][0], v1 = acc[mt][nt][1];
            float v2 = acc[mt][nt][2], v3 = acc[mt][nt][3];
            if (ROUND_OUT) {
                v0 = __uint_as_float(f2tf(v0));
                v1 = __uint_as_float(f2tf(v1));
                v2 = __uint_as_float(f2tf(v2));
                v3 = __uint_as_float(f2tf(v3));
            }
            *(float2*)&C[(size_t)row * N + col] = make_float2(v0, v1);
            *(float2*)&C[(size_t)(row + 8) * N + col] = make_float2(v2, v3);
        }
    }
}

// ---------------------------------------------------------------------------
// Tensor-core causal attention. One block per (64-query tile, head), 8 warps.
// S = Q K^T (tf32 mma), p = exp(clamp(s*0.125,-10,10)-10), O += P V (tf32 mma).
// qkv values are pre-rounded tf32; P rounded before PV.
// ---------------------------------------------------------------------------
#define AS 68   // 68*4=272B = 17*16 (16B-aligned rows, conflict-free frags)
#define ATT_SMEM ((4 * 64 * AS + 64 * 20) * 4)

__global__ __launch_bounds__(256, 2) void attn_mma(const float* __restrict__ qkv,
                                                   float* __restrict__ outp) {
    extern __shared__ float sm[];
    float* Qs = sm;
    float* Ks = Qs + 64 * AS;
    float* Vs = Ks + 64 * AS;
    float* Ps = Vs + 64 * AS;
    float* Lr = Ps + 64 * AS;   // 64 x 20

    const int h = blockIdx.y;
    const int qb = gridDim.x - 1 - blockIdx.x;   // heavy tiles first
    const int q0 = qb * 64;
    const int tid = threadIdx.x;
    const int wid = tid >> 5, lane = tid & 31;
    const int g = lane >> 2, tig = lane & 3;
    const int wR = wid >> 2, wC = wid & 3;       // 2x4 warp grid

    // Q tile load (rounded tf32 already)
#pragma unroll
    for (int i = 0; i < 4; i++) {
        int e = tid + 256 * i;
        int row = e >> 4, c = (e & 15) * 4;
        cp16(&Qs[row * AS + c], &qkv[(size_t)(q0 + row) * QKV_N + h * 64 + c]);
    }
    cp_commit();

    float oacc[2][2][4];
#pragma unroll
    for (int a = 0; a < 2; a++)
#pragma unroll
        for (int b = 0; b < 2; b++)
#pragma unroll
            for (int c = 0; c < 4; c++) oacc[a][b][c] = 0.f;
    float lpart[2][2] = {{0.f, 0.f}, {0.f, 0.f}};

    for (int kb = 0; kb <= qb; kb++) {
        const int k0 = kb * 64;
#pragma unroll
        for (int i = 0; i < 4; i++) {
            int e = tid + 256 * i;
            int row = e >> 4, c = (e & 15) * 4;
            size_t base = (size_t)(k0 + row) * QKV_N + h * 64 + c;
            cp16(&Ks[row * AS + c], &qkv[base + 1024]);
            cp16(&Vs[row * AS + c], &qkv[base + 2048]);
        }
        cp_commit();
        cp_wait<0>();
        __syncthreads();

        // ---- S = Q K^T ----
        float sacc[2][2][4];
#pragma unroll
        for (int a = 0; a < 2; a++)
#pragma unroll
            for (int b = 0; b < 2; b++)
#pragma unroll
                for (int c = 0; c < 4; c++) sacc[a][b][c] = 0.f;

        const uint32_t* Qu = (const uint32_t*)Qs;
        const uint32_t* Ku = (const uint32_t*)Ks;
#pragma unroll
        for (int ks = 0; ks < 8; ks++) {
            uint32_t af[2][4], bf[2][2];
#pragma unroll
            for (int mt = 0; mt < 2; mt++) {
                int r = wR * 32 + mt * 16 + g;
                af[mt][0] = Qu[r * AS + ks * 8 + tig];
                af[mt][1] = Qu[(r + 8) * AS + ks * 8 + tig];
                af[mt][2] = Qu[r * AS + ks * 8 + tig + 4];
                af[mt][3] = Qu[(r + 8) * AS + ks * 8 + tig + 4];
            }
#pragma unroll
            for (int nt = 0; nt < 2; nt++) {
                int r = wC * 16 + nt * 8 + g;
                bf[nt][0] = Ku[r * AS + ks * 8 + tig];
                bf[nt][1] = Ku[r * AS + ks * 8 + tig + 4];
            }
#pragma unroll
            for (int mt = 0; mt < 2; mt++)
#pragma unroll
                for (int nt = 0; nt < 2; nt++)
                    mma8(sacc[mt][nt], af[mt][0], af[mt][1], af[mt][2], af[mt][3],
                         bf[nt][0], bf[nt][1]);
        }

        // ---- softmax numerator + P store (rounded) ----
        const bool diag = (kb == qb);
        uint32_t* Pu = (uint32_t*)Ps;
#pragma unroll
        for (int mt = 0; mt < 2; mt++) {
#pragma unroll
            for (int half = 0; half < 2; half++) {
                int row = wR * 32 + mt * 16 + half * 8 + g;
#pragma unroll
                for (int nt = 0; nt < 2; nt++) {
                    int col = wC * 16 + nt * 8 + tig * 2;
                    float s0 = sacc[mt][nt][half * 2 + 0] * 0.125f;
                    float s1 = sacc[mt][nt][half * 2 + 1] * 0.125f;
                    s0 = fminf(fmaxf(s0, -10.f), 10.f);
                    s1 = fminf(fmaxf(s1, -10.f), 10.f);
                    float e0 = __expf(s0 - 10.f);
                    float e1 = __expf(s1 - 10.f);
                    if (diag && col > row) e0 = 0.f;
                    if (diag && col + 1 > row) e1 = 0.f;
                    uint32_t u0 = f2tf(e0), u1 = f2tf(e1);
                    lpart[mt][half] += __uint_as_float(u0) + __uint_as_float(u1);
                    *(uint2*)&Pu[row * AS + col] = make_uint2(u0, u1);
                }
            }
        }
        __syncthreads();

        // ---- O += P V ----
        const uint32_t* Pc = (const uint32_t*)Ps;
        const uint32_t* Vu = (const uint32_t*)Vs;
#pragma unroll
        for (int ks = 0; ks < 8; ks++) {
            uint32_t af[2][4], bf[2][2];
#pragma unroll
            for (int mt = 0; mt < 2; mt++) {
                int r = wR * 32 + mt * 16 + g;
                af[mt][0] = Pc[r * AS + ks * 8 + tig];
                af[mt][1] = Pc[(r + 8) * AS + ks * 8 + tig];
                af[mt][2] = Pc[r * AS + ks * 8 + tig + 4];
                af[mt][3] = Pc[(r + 8) * AS + ks * 8 + tig + 4];
            }
#pragma unroll
            for (int nt = 0; nt < 2; nt++) {
                int col = wC * 16 + nt * 8 + g;
                bf[nt][0] = Vu[(ks * 8 + tig) * AS + col];
                bf[nt][1] = Vu[(ks * 8 + tig + 4) * AS + col];
            }
#pragma unroll
            for (int mt = 0; mt < 2; mt++)
#pragma unroll
                for (int nt = 0; nt < 2; nt++)
                    mma8(oacc[mt][nt], af[mt][0], af[mt][1], af[mt][2], af[mt][3],
                         bf[nt][0], bf[nt][1]);
        }
        __syncthreads();  // protect Ks/Vs/Ps before next iteration's loads
    }

    // ---- deterministic L reduction + output (rounded tf32) ----
#pragma unroll
    for (int mt = 0; mt < 2; mt++)
#pragma unroll
        for (int half = 0; half < 2; half++) {
            int row = wR * 32 + mt * 16 + half * 8 + g;
            Lr[row * 20 + wC * 4 + tig] = lpart[mt][half];
        }
    __syncthreads();

#pragma unroll
    for (int mt = 0; mt < 2; mt++) {
#pragma unroll
        for (int half = 0; half < 2; half++) {
            int row = wR * 32 + mt * 16 + half * 8 + g;
            float s = 0.f;
#pragma unroll
            for (int t = 0; t < 16; t++) s += Lr[row * 20 + t];
            float inv = 1.f / s;
#pragma unroll
            for (int nt = 0; nt < 2; nt++) {
                int col = wC * 16 + nt * 8 + tig * 2;
                uint2 u;
                u.x = f2tf(oacc[mt][nt][half * 2 + 0] * inv);
                u.y = f2tf(oacc[mt][nt][half * 2 + 1] * inv);
                *(uint2*)&outp[(size_t)(q0 + row) * D_MODEL + h * 64 + col] = u;
            }
        }
    }
}

// ---------------------------------------------------------------------------
// Launch
// ---------------------------------------------------------------------------
extern "C" void kernel_launch(void* const* d_in, const int* in_sizes, int n_in,
                              void* d_out, int out_size) {
    const float* x    = (const float*)d_in[0];   // [4096,1024]
    const float* Wqkv = (const float*)d_in[1];   // [3072,1024]
    const float* Wout = (const float*)d_in[2];   // [1024,1024]
    float* out = (float*)d_out;                  // [4096,1024]

    float *qkv, *attn, *xr, *wqkvr, *woutr;
    cudaGetSymbolAddress((void**)&qkv, g_qkv);
    cudaGetSymbolAddress((void**)&attn, g_attn);
    cudaGetSymbolAddress((void**)&xr, g_xr);
    cudaGetSymbolAddress((void**)&wqkvr, g_wqkvr);
    cudaGetSymbolAddress((void**)&woutr, g_woutr);

    cudaFuncSetAttribute(gemm_tf32<true>, cudaFuncAttributeMaxDynamicSharedMemorySize, GEMM_SMEM);
    cudaFuncSetAttribute(gemm_tf32<false>, cudaFuncAttributeMaxDynamicSharedMemorySize, GEMM_SMEM);
    cudaFuncSetAttribute(attn_mma, cudaFuncAttributeMaxDynamicSharedMemorySize, ATT_SMEM);

    // 0) round inputs to tf32 (rna)
    round_k<<<(T_TOK * D_MODEL / 4 + 255) / 256, 256>>>((const float4*)x, (float4*)xr,
                                                        T_TOK * D_MODEL / 4);
    round_k<<<(QKV_N * D_MODEL / 4 + 255) / 256, 256>>>((const float4*)Wqkv, (float4*)wqkvr,
                                                        QKV_N * D_MODEL / 4);
    round_k<<<(D_MODEL * D_MODEL / 4 + 255) / 256, 256>>>((const float4*)Wout, (float4*)woutr,
                                                          D_MODEL * D_MODEL / 4);

    // 1) QKV projection (rounded output feeds attention mmas)
    gemm_tf32<true><<<dim3(QKV_N / 128, T_TOK / 128), 256, GEMM_SMEM>>>(
        xr, wqkvr, qkv, T_TOK, QKV_N, D_MODEL);

    // 2) causal clamped attention (tensor core)
    attn_mma<<<dim3(T_TOK / 64, NH), 256, ATT_SMEM>>>(qkv, attn);

    // 3) output projection (full fp32 out)
    gemm_tf32<false><<<dim3(D_MODEL / 128, T_TOK / 128), 256, GEMM_SMEM>>>(
        attn, woutr, out, T_TOK, D_MODEL, D_MODEL);
}

// round 4
// speedup vs baseline: 3.0468x; 1.0127x over previous
#include <cuda_runtime.h>
#include <cstdint>

#define T_TOK 4096
#define D_MODEL 1024
#define NH 16
#define QKV_N 3072

// Scratch (__device__ globals per allocation rules)
__device__ float g_qkv[T_TOK * QKV_N];      // rounded-tf32 q|k|v
__device__ float g_attn[T_TOK * D_MODEL];   // rounded-tf32 attention out
__device__ float g_xr[T_TOK * D_MODEL];     // rounded inputs
__device__ float g_wqkvr[QKV_N * D_MODEL];
__device__ float g_woutr[D_MODEL * D_MODEL];

// ---------------------------------------------------------------------------
// helpers
// ---------------------------------------------------------------------------
__device__ __forceinline__ uint32_t f2tf(float f) {
    uint32_t u; asm("cvt.rna.tf32.f32 %0, %1;" : "=r"(u) : "f"(f)); return u;
}
__device__ __forceinline__ void cp16(void* smem, const void* gmem) {
    uint32_t s = (uint32_t)__cvta_generic_to_shared(smem);
    asm volatile("cp.async.cg.shared.global [%0], [%1], 16;" :: "r"(s), "l"(gmem));
}
__device__ __forceinline__ void cp_commit() { asm volatile("cp.async.commit_group;"); }
template <int N> __device__ __forceinline__ void cp_wait() {
    asm volatile("cp.async.wait_group %0;" :: "n"(N));
}
// D += A*B, m16n8k8 tf32 (A row-major, B col-major)
__device__ __forceinline__ void mma8(float* c, uint32_t a0, uint32_t a1, uint32_t a2,
                                     uint32_t a3, uint32_t b0, uint32_t b1) {
    asm("mma.sync.aligned.m16n8k8.row.col.f32.tf32.tf32.f32 "
        "{%0,%1,%2,%3}, {%4,%5,%6,%7}, {%8,%9}, {%0,%1,%2,%3};"
        : "+f"(c[0]), "+f"(c[1]), "+f"(c[2]), "+f"(c[3])
        : "r"(a0), "r"(a1), "r"(a2), "r"(a3), "r"(b0), "r"(b1));
}

// ---------------------------------------------------------------------------
// elementwise rna(tf32) rounding
// ---------------------------------------------------------------------------
__global__ void round_k(const float4* __restrict__ in, float4* __restrict__ out, int n4) {
    int i = blockIdx.x * blockDim.x + threadIdx.x;
    if (i >= n4) return;
    float4 v = in[i];
    uint4 o = {f2tf(v.x), f2tf(v.y), f2tf(v.z), f2tf(v.w)};
    out[i] = *reinterpret_cast<float4*>(&o);
}

// ---------------------------------------------------------------------------
// tf32 tensor-core GEMM (NT): C[m,n] = sum_k A[m,k]*B[n,k]
// 128x128x32 block tile, 256 threads (8 warps, 2x4), double-buffered cp.async
// with load(kt+1) issued after the single barrier -> full compute overlap.
// ---------------------------------------------------------------------------
#define SA 36   // smem row stride (floats), conflict-free
#define GEMM_SMEM (2 * 2 * 128 * SA * 4)

template <bool ROUND_OUT>
__global__ __launch_bounds__(256, 2) void gemm_tf32(const float* __restrict__ A,
                                                    const float* __restrict__ B,
                                                    float* __restrict__ C,
                                                    int M, int N, int K) {
    extern __shared__ float sm[];
    float* Abuf[2] = {sm, sm + 2 * 128 * SA};
    float* Bbuf[2] = {sm + 128 * SA, sm + 3 * 128 * SA};

    const int tid = threadIdx.x;
    const int wid = tid >> 5, lane = tid & 31;
    const int g = lane >> 2, tig = lane & 3;
    const int mW = (wid >> 2) * 64, nW = (wid & 3) * 32;
    const int by = blockIdx.y * 128, bx = blockIdx.x * 128;

    float acc[4][4][4];
#pragma unroll
    for (int a = 0; a < 4; a++)
#pragma unroll
        for (int b = 0; b < 4; b++)
#pragma unroll
            for (int c = 0; c < 4; c++) acc[a][b][c] = 0.f;

    const int nkt = K / 32;

    auto load_tile = [&](int kt, int buf) {
        const float* Ag = A + (size_t)by * K + kt * 32;
        const float* Bg = B + (size_t)bx * K + kt * 32;
#pragma unroll
        for (int i = 0; i < 4; i++) {
            int e = tid + 256 * i;
            int row = e >> 3, c = (e & 7) * 4;
            cp16(&Abuf[buf][row * SA + c], Ag + (size_t)row * K + c);
            cp16(&Bbuf[buf][row * SA + c], Bg + (size_t)row * K + c);
        }
        cp_commit();
    };

    load_tile(0, 0);
    for (int kt = 0; kt < nkt; kt++) {
        cp_wait<0>();
        __syncthreads();
        // prefetch next tile; overlaps the whole compute below.
        // safe: all warps passed the barrier, so iter kt-1 reads of this
        // buffer are complete.
        if (kt + 1 < nkt) load_tile(kt + 1, (kt + 1) & 1);

        const uint32_t* As = (const uint32_t*)Abuf[kt & 1];
        const uint32_t* Bs = (const uint32_t*)Bbuf[kt & 1];
#pragma unroll
        for (int ks = 0; ks < 4; ks++) {
            uint32_t af[4][4], bf[4][2];
#pragma unroll
            for (int mt = 0; mt < 4; mt++) {
                int r = mW + mt * 16 + g;
                af[mt][0] = As[r * SA + ks * 8 + tig];
                af[mt][1] = As[(r + 8) * SA + ks * 8 + tig];
                af[mt][2] = As[r * SA + ks * 8 + tig + 4];
                af[mt][3] = As[(r + 8) * SA + ks * 8 + tig + 4];
            }
#pragma unroll
            for (int nt = 0; nt < 4; nt++) {
                int r = nW + nt * 8 + g;
                bf[nt][0] = Bs[r * SA + ks * 8 + tig];
                bf[nt][1] = Bs[r * SA + ks * 8 + tig + 4];
            }
#pragma unroll
            for (int mt = 0; mt < 4; mt++)
#pragma unroll
                for (int nt = 0; nt < 4; nt++)
                    mma8(acc[mt][nt], af[mt][0], af[mt][1], af[mt][2], af[mt][3],
                         bf[nt][0], bf[nt][1]);
        }
    }

#pragma unroll
    for (int mt = 0; mt < 4; mt++) {
#pragma unroll
        for (int nt = 0; nt < 4; nt++) {
            int row = by + mW + mt * 16 + g;
            int col = bx + nW + nt * 8 + tig * 2;
            float v0 = acc[mt][nt][0], v1 = acc[mt][nt][1];
            float v2 = acc[mt][nt][2], v3 = acc[mt][nt][3];
            if (ROUND_OUT) {
                v0 = __uint_as_float(f2tf(v0));
                v1 = __uint_as_float(f2tf(v1));
                v2 = __uint_as_float(f2tf(v2));
                v3 = __uint_as_float(f2tf(v3));
            }
            *(float2*)&C[(size_t)row * N + col] = make_float2(v0, v1);
            *(float2*)&C[(size_t)(row + 8) * N + col] = make_float2(v2, v3);
        }
    }
}

// ---------------------------------------------------------------------------
// Tensor-core causal attention, double-buffered K/V, 2 barriers per k-tile.
// One block per (64-query tile, head), 8 warps (2x4), warp tile 32x16.
// ---------------------------------------------------------------------------
#define AS 68
// Q(64) + K(2x64) + V(2x64) + P(64) rows of AS floats, + Lred
#define ATT_SMEM ((6 * 64 * AS + 64 * 20) * 4)

__global__ __launch_bounds__(256, 2) void attn_mma(const float* __restrict__ qkv,
                                                   float* __restrict__ outp) {
    extern __shared__ float sm[];
    float* Qs = sm;
    float* Kb[2] = {Qs + 64 * AS, Qs + 2 * 64 * AS};
    float* Vb[2] = {Qs + 3 * 64 * AS, Qs + 4 * 64 * AS};
    float* Ps = Qs + 5 * 64 * AS;
    float* Lr = Ps + 64 * AS;   // 64 x 20

    const int h = blockIdx.y;
    const int qb = gridDim.x - 1 - blockIdx.x;   // heavy tiles first
    const int q0 = qb * 64;
    const int tid = threadIdx.x;
    const int wid = tid >> 5, lane = tid & 31;
    const int g = lane >> 2, tig = lane & 3;
    const int wR = wid >> 2, wC = wid & 3;       // 2x4 warp grid

    const int nkb = qb + 1;

    auto load_kv = [&](int kb, int buf) {
        const int k0 = kb * 64;
#pragma unroll
        for (int i = 0; i < 4; i++) {
            int e = tid + 256 * i;
            int row = e >> 4, c = (e & 15) * 4;
            size_t base = (size_t)(k0 + row) * QKV_N + h * 64 + c;
            cp16(&Kb[buf][row * AS + c], &qkv[base + 1024]);
            cp16(&Vb[buf][row * AS + c], &qkv[base + 2048]);
        }
        cp_commit();
    };

    // group 0: Q + K/V(0)
#pragma unroll
    for (int i = 0; i < 4; i++) {
        int e = tid + 256 * i;
        int row = e >> 4, c = (e & 15) * 4;
        cp16(&Qs[row * AS + c], &qkv[(size_t)(q0 + row) * QKV_N + h * 64 + c]);
    }
    load_kv(0, 0);  // commits Q + KV0 together

    float oacc[2][2][4];
#pragma unroll
    for (int a = 0; a < 2; a++)
#pragma unroll
        for (int b = 0; b < 2; b++)
#pragma unroll
            for (int c = 0; c < 4; c++) oacc[a][b][c] = 0.f;
    float lpart[2][2] = {{0.f, 0.f}, {0.f, 0.f}};

    for (int kb = 0; kb < nkb; kb++) {
        cp_wait<0>();
        __syncthreads();                          // barrier 1: data ready + prev iter done
        if (kb + 1 < nkb) load_kv(kb + 1, (kb + 1) & 1);  // overlaps all compute below

        const uint32_t* Qu = (const uint32_t*)Qs;
        const uint32_t* Ku = (const uint32_t*)Kb[kb & 1];
        const uint32_t* Vu = (const uint32_t*)Vb[kb & 1];

        // ---- S = Q K^T ----
        float sacc[2][2][4];
#pragma unroll
        for (int a = 0; a < 2; a++)
#pragma unroll
            for (int b = 0; b < 2; b++)
#pragma unroll
                for (int c = 0; c < 4; c++) sacc[a][b][c] = 0.f;

#pragma unroll
        for (int ks = 0; ks < 8; ks++) {
            uint32_t af[2][4], bf[2][2];
#pragma unroll
            for (int mt = 0; mt < 2; mt++) {
                int r = wR * 32 + mt * 16 + g;
                af[mt][0] = Qu[r * AS + ks * 8 + tig];
                af[mt][1] = Qu[(r + 8) * AS + ks * 8 + tig];
                af[mt][2] = Qu[r * AS + ks * 8 + tig + 4];
                af[mt][3] = Qu[(r + 8) * AS + ks * 8 + tig + 4];
            }
#pragma unroll
            for (int nt = 0; nt < 2; nt++) {
                int r = wC * 16 + nt * 8 + g;
                bf[nt][0] = Ku[r * AS + ks * 8 + tig];
                bf[nt][1] = Ku[r * AS + ks * 8 + tig + 4];
            }
#pragma unroll
            for (int mt = 0; mt < 2; mt++)
#pragma unroll
                for (int nt = 0; nt < 2; nt++)
                    mma8(sacc[mt][nt], af[mt][0], af[mt][1], af[mt][2], af[mt][3],
                         bf[nt][0], bf[nt][1]);
        }

        // ---- softmax numerator + P store (rounded tf32) ----
        const bool diag = (kb == qb);
        uint32_t* Pu = (uint32_t*)Ps;
#pragma unroll
        for (int mt = 0; mt < 2; mt++) {
#pragma unroll
            for (int half = 0; half < 2; half++) {
                int row = wR * 32 + mt * 16 + half * 8 + g;
#pragma unroll
                for (int nt = 0; nt < 2; nt++) {
                    int col = wC * 16 + nt * 8 + tig * 2;
                    float s0 = sacc[mt][nt][half * 2 + 0] * 0.125f;
                    float s1 = sacc[mt][nt][half * 2 + 1] * 0.125f;
                    s0 = fminf(fmaxf(s0, -10.f), 10.f);
                    s1 = fminf(fmaxf(s1, -10.f), 10.f);
                    float e0 = __expf(s0 - 10.f);
                    float e1 = __expf(s1 - 10.f);
                    if (diag && col > row) e0 = 0.f;
                    if (diag && col + 1 > row) e1 = 0.f;
                    uint32_t u0 = f2tf(e0), u1 = f2tf(e1);
                    lpart[mt][half] += __uint_as_float(u0) + __uint_as_float(u1);
                    *(uint2*)&Pu[row * AS + col] = make_uint2(u0, u1);
                }
            }
        }
        __syncthreads();                          // barrier 2: P visible

        // ---- O += P V ----
        const uint32_t* Pc = (const uint32_t*)Ps;
#pragma unroll
        for (int ks = 0; ks < 8; ks++) {
            uint32_t af[2][4], bf[2][2];
#pragma unroll
            for (int mt = 0; mt < 2; mt++) {
                int r = wR * 32 + mt * 16 + g;
                af[mt][0] = Pc[r * AS + ks * 8 + tig];
                af[mt][1] = Pc[(r + 8) * AS + ks * 8 + tig];
                af[mt][2] = Pc[r * AS + ks * 8 + tig + 4];
                af[mt][3] = Pc[(r + 8) * AS + ks * 8 + tig + 4];
            }
#pragma unroll
            for (int nt = 0; nt < 2; nt++) {
                int col = wC * 16 + nt * 8 + g;
                bf[nt][0] = Vu[(ks * 8 + tig) * AS + col];
                bf[nt][1] = Vu[(ks * 8 + tig + 4) * AS + col];
            }
#pragma unroll
            for (int mt = 0; mt < 2; mt++)
#pragma unroll
                for (int nt = 0; nt < 2; nt++)
                    mma8(oacc[mt][nt], af[mt][0], af[mt][1], af[mt][2], af[mt][3],
                         bf[nt][0], bf[nt][1]);
        }
        // no end barrier: next iteration's barrier 1 covers buffer reuse
    }

    // ---- deterministic L reduction + output (rounded tf32) ----
#pragma unroll
    for (int mt = 0; mt < 2; mt++)
#pragma unroll
        for (int half = 0; half < 2; half++) {
            int row = wR * 32 + mt * 16 + half * 8 + g;
            Lr[row * 20 + wC * 4 + tig] = lpart[mt][half];
        }
    __syncthreads();

#pragma unroll
    for (int mt = 0; mt < 2; mt++) {
#pragma unroll
        for (int half = 0; half < 2; half++) {
            int row = wR * 32 + mt * 16 + half * 8 + g;
            float s = 0.f;
#pragma unroll
            for (int t = 0; t < 16; t++) s += Lr[row * 20 + t];
            float inv = 1.f / s;
#pragma unroll
            for (int nt = 0; nt < 2; nt++) {
                int col = wC * 16 + nt * 8 + tig * 2;
                uint2 u;
                u.x = f2tf(oacc[mt][nt][half * 2 + 0] * inv);
                u.y = f2tf(oacc[mt][nt][half * 2 + 1] * inv);
                *(uint2*)&outp[(size_t)(q0 + row) * D_MODEL + h * 64 + col] = u;
            }
        }
    }
}

// ---------------------------------------------------------------------------
// Launch
// ---------------------------------------------------------------------------
extern "C" void kernel_launch(void* const* d_in, const int* in_sizes, int n_in,
                              void* d_out, int out_size) {
    const float* x    = (const float*)d_in[0];   // [4096,1024]
    const float* Wqkv = (const float*)d_in[1];   // [3072,1024]
    const float* Wout = (const float*)d_in[2];   // [1024,1024]
    float* out = (float*)d_out;                  // [4096,1024]

    float *qkv, *attn, *xr, *wqkvr, *woutr;
    cudaGetSymbolAddress((void**)&qkv, g_qkv);
    cudaGetSymbolAddress((void**)&attn, g_attn);
    cudaGetSymbolAddress((void**)&xr, g_xr);
    cudaGetSymbolAddress((void**)&wqkvr, g_wqkvr);
    cudaGetSymbolAddress((void**)&woutr, g_woutr);

    cudaFuncSetAttribute(gemm_tf32<true>, cudaFuncAttributeMaxDynamicSharedMemorySize, GEMM_SMEM);
    cudaFuncSetAttribute(gemm_tf32<false>, cudaFuncAttributeMaxDynamicSharedMemorySize, GEMM_SMEM);
    cudaFuncSetAttribute(attn_mma, cudaFuncAttributeMaxDynamicSharedMemorySize, ATT_SMEM);

    // 0) round inputs to tf32 (rna)
    round_k<<<(T_TOK * D_MODEL / 4 + 255) / 256, 256>>>((const float4*)x, (float4*)xr,
                                                        T_TOK * D_MODEL / 4);
    round_k<<<(QKV_N * D_MODEL / 4 + 255) / 256, 256>>>((const float4*)Wqkv, (float4*)wqkvr,
                                                        QKV_N * D_MODEL / 4);
    round_k<<<(D_MODEL * D_MODEL / 4 + 255) / 256, 256>>>((const float4*)Wout, (float4*)woutr,
                                                          D_MODEL * D_MODEL / 4);

    // 1) QKV projection (rounded output feeds attention mmas)
    gemm_tf32<true><<<dim3(QKV_N / 128, T_TOK / 128), 256, GEMM_SMEM>>>(
        xr, wqkvr, qkv, T_TOK, QKV_N, D_MODEL);

    // 2) causal clamped attention (tensor core)
    attn_mma<<<dim3(T_TOK / 64, NH), 256, ATT_SMEM>>>(qkv, attn);

    // 3) output projection (full fp32 out)
    gemm_tf32<false><<<dim3(D_MODEL / 128, T_TOK / 128), 256, GEMM_SMEM>>>(
        attn, woutr, out, T_TOK, D_MODEL, D_MODEL);
}